// round 2
// baseline (speedup 1.0000x reference)
#include <cuda_runtime.h>
#include <math.h>

#define S_DIM 2048
#define B_DIM 32
#define H_DIM 1024
#define K_DIM 2048                 // 2*H
#define M_DIM (S_DIM * B_DIM)      // 65536

#define BM 128
#define BN 128
#define BK 16
#define NCHUNKS (H_DIM / BN)       // 8

// Scratch (no allocations allowed in kernel_launch)
__device__ float g_hproj[B_DIM * H_DIM];
__device__ float g_scores[B_DIM * S_DIM];

typedef unsigned long long u64;

__device__ __forceinline__ u64 pack2(float lo, float hi) {
    u64 r;
    asm("mov.b64 %0, {%1, %2};" : "=l"(r) : "f"(lo), "f"(hi));
    return r;
}
__device__ __forceinline__ void unpack2(u64 v, float& lo, float& hi) {
    asm("mov.b64 {%0, %1}, %2;" : "=f"(lo), "=f"(hi) : "l"(v));
}
// Packed fp32x2 FMA (Blackwell FFMA2 — only reachable via PTX fma.rn.f32x2)
__device__ __forceinline__ void fma2(u64& d, u64 a, u64 b) {
    asm("fma.rn.f32x2 %0, %1, %2, %3;" : "=l"(d) : "l"(a), "l"(b), "l"(d));
}

// ---------------------------------------------------------------------------
// Kernel 1: h_proj[b][h] = bias[h] + sum_e hidden[b][e] * W[e][h]   (Wh = W[:H])
// ---------------------------------------------------------------------------
__global__ void hproj_kernel(const float* __restrict__ hidden,
                             const float* __restrict__ W,
                             const float* __restrict__ bias) {
    int g = blockIdx.x * blockDim.x + threadIdx.x;   // 0..32767
    int b = g >> 10;
    int h = g & 1023;
    const float* hrow = hidden + b * H_DIM;
    float acc = bias[h];
#pragma unroll 8
    for (int e = 0; e < H_DIM; e++)
        acc += hrow[e] * W[(size_t)e * H_DIM + h];
    g_hproj[g] = acc;
}

// ---------------------------------------------------------------------------
// Kernel 2: fused  scores[b][s] = sum_h v[h] * tanh( (enc_row @ We)[h] + hproj[b][h] )
// GEMM: M=65536 rows (row = s*32+b), K=2048, N=1024. N is looped in 8 chunks of 128;
// the C tile never leaves registers.
// ---------------------------------------------------------------------------
__global__ __launch_bounds__(256, 2)
void score_kernel(const float* __restrict__ enc,
                  const float* __restrict__ W,
                  const float* __restrict__ v) {
    __shared__ float As[BK][BM];   // A transposed: As[k][m]
    __shared__ float Bs[BK][BN];   // Bs[k][n]

    const int t  = threadIdx.x;
    const int tx = t & 15;         // n direction (16)
    const int ty = t >> 4;         // m direction (16)
    const int bm = blockIdx.x * BM;
    const float* Wp = W + (size_t)H_DIM * H_DIM;   // We base: W[(H+e)*H + n]

    float rs[8];
#pragma unroll
    for (int i = 0; i < 8; i++) rs[i] = 0.f;

    for (int nc = 0; nc < NCHUNKS; nc++) {
        const int n0 = nc * BN;
        u64 acc[8][4];
#pragma unroll
        for (int i = 0; i < 8; i++)
#pragma unroll
            for (int j = 0; j < 4; j++) acc[i][j] = 0ull;

        for (int k0 = 0; k0 < K_DIM; k0 += BK) {
            __syncthreads();
            // Load A tile: 128 rows x 16 k  (512 float4, 2 per thread), store transposed
#pragma unroll
            for (int it = 0; it < 2; it++) {
                int idx = t + it * 256;
                int i  = idx >> 2;
                int kq = idx & 3;
                float4 va = *reinterpret_cast<const float4*>(
                    &enc[(size_t)(bm + i) * K_DIM + k0 + kq * 4]);
                As[kq * 4 + 0][i] = va.x;
                As[kq * 4 + 1][i] = va.y;
                As[kq * 4 + 2][i] = va.z;
                As[kq * 4 + 3][i] = va.w;
            }
            // Load B tile: 16 k x 128 n (512 float4, 2 per thread)
#pragma unroll
            for (int it = 0; it < 2; it++) {
                int idx = t + it * 256;
                int k  = idx >> 5;
                int nq = idx & 31;
                *reinterpret_cast<float4*>(&Bs[k][nq * 4]) =
                    *reinterpret_cast<const float4*>(
                        &Wp[(size_t)(k0 + k) * H_DIM + n0 + nq * 4]);
            }
            __syncthreads();

#pragma unroll
            for (int k = 0; k < BK; k++) {
                float4 a0 = *reinterpret_cast<const float4*>(&As[k][ty * 8]);
                float4 a1 = *reinterpret_cast<const float4*>(&As[k][ty * 8 + 4]);
                u64 a2[8];
                a2[0] = pack2(a0.x, a0.x);
                a2[1] = pack2(a0.y, a0.y);
                a2[2] = pack2(a0.z, a0.z);
                a2[3] = pack2(a0.w, a0.w);
                a2[4] = pack2(a1.x, a1.x);
                a2[5] = pack2(a1.y, a1.y);
                a2[6] = pack2(a1.z, a1.z);
                a2[7] = pack2(a1.w, a1.w);
                const u64* bp = reinterpret_cast<const u64*>(&Bs[k][tx * 8]);
                u64 b2[4] = {bp[0], bp[1], bp[2], bp[3]};
#pragma unroll
                for (int i = 0; i < 8; i++)
#pragma unroll
                    for (int j = 0; j < 4; j++)
                        fma2(acc[i][j], a2[i], b2[j]);
            }
        }

        // Epilogue for this N chunk: tanh + weighted reduce over the 128 n's
#pragma unroll
        for (int i = 0; i < 8; i++) {
            int r = bm + ty * 8 + i;
            int b = r & 31;
            const float* hp = g_hproj + (size_t)b * H_DIM + n0 + tx * 8;
            const float* vp = v + n0 + tx * 8;
            float s = 0.f;
#pragma unroll
            for (int j = 0; j < 4; j++) {
                float c0, c1;
                unpack2(acc[i][j], c0, c1);
                s += vp[j * 2]     * tanhf(c0 + hp[j * 2]);
                s += vp[j * 2 + 1] * tanhf(c1 + hp[j * 2 + 1]);
            }
            // Butterfly reduce across the 16 tx lanes (stays inside half-warp)
#pragma unroll
            for (int off = 8; off > 0; off >>= 1)
                s += __shfl_xor_sync(0xffffffffu, s, off);
            rs[i] += s;
        }
    }

    if (tx == 0) {
#pragma unroll
        for (int i = 0; i < 8; i++) {
            int r = bm + ty * 8 + i;            // r = s*32 + b
            g_scores[(r & 31) * S_DIM + (r >> 5)] = rs[i];
        }
    }
}

// ---------------------------------------------------------------------------
// Kernel 3: row softmax over S for each of the 32 batch rows
// ---------------------------------------------------------------------------
__global__ void softmax_kernel(float* __restrict__ out) {
    __shared__ float red[256];
    const int b = blockIdx.x;
    const int t = threadIdx.x;
    const float* row = g_scores + (size_t)b * S_DIM;
    float* orow = out + (size_t)b * S_DIM;

    float m = -INFINITY;
    for (int i = t; i < S_DIM; i += 256) m = fmaxf(m, row[i]);
    red[t] = m;
    __syncthreads();
    for (int o = 128; o > 0; o >>= 1) {
        if (t < o) red[t] = fmaxf(red[t], red[t + o]);
        __syncthreads();
    }
    m = red[0];
    __syncthreads();

    float sum = 0.f;
    for (int i = t; i < S_DIM; i += 256) {
        float e = expf(row[i] - m);
        orow[i] = e;
        sum += e;
    }
    red[t] = sum;
    __syncthreads();
    for (int o = 128; o > 0; o >>= 1) {
        if (t < o) red[t] += red[t + o];
        __syncthreads();
    }
    float inv = 1.f / red[0];
    __syncthreads();
    for (int i = t; i < S_DIM; i += 256) orow[i] *= inv;
}

// ---------------------------------------------------------------------------
extern "C" void kernel_launch(void* const* d_in, const int* in_sizes, int n_in,
                              void* d_out, int out_size) {
    const float* hidden = (const float*)d_in[0];   // (B, H)
    const float* enc    = (const float*)d_in[1];   // (S, B, 2H)
    const float* W      = (const float*)d_in[2];   // (3H, H)
    const float* bias   = (const float*)d_in[3];   // (H,)
    const float* v      = (const float*)d_in[4];   // (H,)
    float* out = (float*)d_out;                    // (B, S)

    hproj_kernel<<<(B_DIM * H_DIM) / 256, 256>>>(hidden, W, bias);
    score_kernel<<<M_DIM / BM, 256>>>(enc, W, v);
    softmax_kernel<<<B_DIM, 256>>>(out);
}

// round 4
// speedup vs baseline: 3.0458x; 3.0458x over previous
#include <cuda_runtime.h>
#include <cuda_bf16.h>
#include <cstdint>
#include <math.h>

#define S_DIM 2048
#define B_DIM 32
#define H_DIM 1024
#define K_DIM 2048
#define M_DIM 65536

#define BM 128
#define BN 128
#define BKT 32
#define KTILES (K_DIM / BKT)     // 64
#define STAGES 3
#define THREADS 256
#define NTILES (H_DIM / BN)      // 8

// stage parts (bytes): Ah | Al | Bh | Bl, each 128 rows x 32 bf16 = 8KB
#define PART_A_H 0
#define PART_A_L 8192
#define PART_B_H 16384
#define PART_B_L 24576
#define STAGE_BYTES 32768
#define DSMEM_BYTES (STAGES * STAGE_BYTES)

// ---------------- device scratch ----------------
__device__ __nv_bfloat16 g_Ah[(size_t)M_DIM * K_DIM];
__device__ __nv_bfloat16 g_Al[(size_t)M_DIM * K_DIM];
__device__ __nv_bfloat16 g_Bh[(size_t)H_DIM * K_DIM];
__device__ __nv_bfloat16 g_Bl[(size_t)H_DIM * K_DIM];
__device__ float g_hprojT[H_DIM * B_DIM];     // [h][b]
__device__ float g_part[NTILES * M_DIM];      // per-N-tile partial scores [nt][m]

// ---------------- PTX helpers (baseline sm_80+ only) ----------------
__device__ __forceinline__ uint32_t smem_u32(const void* p) {
    uint32_t a;
    asm("{ .reg .u64 t; cvta.to.shared.u64 t, %1; cvt.u32.u64 %0, t; }" : "=r"(a) : "l"(p));
    return a;
}
__device__ __forceinline__ void cp16(uint32_t dst, const void* src) {
    asm volatile("cp.async.cg.shared.global [%0], [%1], 16;" :: "r"(dst), "l"(src) : "memory");
}
__device__ __forceinline__ void cp_commit() {
    asm volatile("cp.async.commit_group;" ::: "memory");
}
__device__ __forceinline__ void cp_wait1() {
    asm volatile("cp.async.wait_group 1;" ::: "memory");
}
__device__ __forceinline__ void ldsm4(uint32_t* r, uint32_t addr) {
    asm volatile("ldmatrix.sync.aligned.m8n8.x4.shared.b16 {%0,%1,%2,%3}, [%4];"
                 : "=r"(r[0]), "=r"(r[1]), "=r"(r[2]), "=r"(r[3]) : "r"(addr));
}
__device__ __forceinline__ void mma_bf16(float* c, const uint32_t* a, uint32_t b0, uint32_t b1) {
    asm volatile("mma.sync.aligned.m16n8k16.row.col.f32.bf16.bf16.f32 "
                 "{%0,%1,%2,%3}, {%4,%5,%6,%7}, {%8,%9}, {%0,%1,%2,%3};"
                 : "+f"(c[0]), "+f"(c[1]), "+f"(c[2]), "+f"(c[3])
                 : "r"(a[0]), "r"(a[1]), "r"(a[2]), "r"(a[3]), "r"(b0), "r"(b1));
}

// swizzled 16B-unit offset inside a 128x32 bf16 tile (conflict-free for
// ldmatrix 8-row phases and for the cp.async store pattern)
__device__ __forceinline__ uint32_t tile_off(int row, int c) {
    return (uint32_t)(((row << 2) + (c ^ ((row >> 1) & 3))) << 4);
}

// ---------------------------------------------------------------------------
// Pre-split A (enc, fp32) -> bf16 hi/lo, same [m][k] layout
// ---------------------------------------------------------------------------
__global__ void asplit_kernel(const float* __restrict__ enc) {
    size_t g = ((size_t)blockIdx.x * 256 + threadIdx.x) * 8;
    float4 f0 = *reinterpret_cast<const float4*>(enc + g);
    float4 f1 = *reinterpret_cast<const float4*>(enc + g + 4);
    float x[8] = {f0.x, f0.y, f0.z, f0.w, f1.x, f1.y, f1.z, f1.w};
    uint32_t hh[4], ll[4];
#pragma unroll
    for (int i = 0; i < 4; i++) {
        __nv_bfloat162 h = __floats2bfloat162_rn(x[2 * i], x[2 * i + 1]);
        float2 hf = __bfloat1622float2(h);
        __nv_bfloat162 l = __floats2bfloat162_rn(x[2 * i] - hf.x, x[2 * i + 1] - hf.y);
        hh[i] = *reinterpret_cast<uint32_t*>(&h);
        ll[i] = *reinterpret_cast<uint32_t*>(&l);
    }
    *reinterpret_cast<uint4*>(&g_Ah[g]) = make_uint4(hh[0], hh[1], hh[2], hh[3]);
    *reinterpret_cast<uint4*>(&g_Al[g]) = make_uint4(ll[0], ll[1], ll[2], ll[3]);
}

// ---------------------------------------------------------------------------
// Pre-split + transpose We -> g_Bh/g_Bl [n][k], smem tile transpose
// ---------------------------------------------------------------------------
__global__ void bsplit_kernel(const float* __restrict__ W) {
    __shared__ float tile[32][33];
    const int k0 = blockIdx.x * 32;
    const int n0 = blockIdx.y * 32;
    const int tx = threadIdx.x;        // 32
    const int ty = threadIdx.y;        // 8
#pragma unroll
    for (int r = 0; r < 4; r++) {
        int k = ty * 4 + r;
        tile[k][tx] = W[(size_t)(H_DIM + k0 + k) * H_DIM + n0 + tx];
    }
    __syncthreads();
#pragma unroll
    for (int r = 0; r < 4; r++) {
        int n = ty * 4 + r;
        float w = tile[tx][n];
        __nv_bfloat16 h = __float2bfloat16_rn(w);
        float l = w - __bfloat162float(h);
        size_t o = (size_t)(n0 + n) * K_DIM + k0 + tx;
        g_Bh[o] = h;
        g_Bl[o] = __float2bfloat16_rn(l);
    }
}

// ---------------------------------------------------------------------------
// hproj (transposed) : g_hprojT[h][b] = bias[h] + sum_e hidden[b][e] W[e][h]
// ---------------------------------------------------------------------------
__global__ void hproj_kernel(const float* __restrict__ hidden,
                             const float* __restrict__ W,
                             const float* __restrict__ bias) {
    int g = blockIdx.x * 256 + threadIdx.x;    // 0..8191
    int b = g >> 8;
    int h4 = (g & 255) * 4;
    const float* hr = hidden + b * H_DIM;
    float4 acc = make_float4(bias[h4], bias[h4 + 1], bias[h4 + 2], bias[h4 + 3]);
#pragma unroll 16
    for (int e = 0; e < H_DIM; e++) {
        float f = hr[e];
        float4 w = *reinterpret_cast<const float4*>(&W[(size_t)e * H_DIM + h4]);
        acc.x += f * w.x; acc.y += f * w.y; acc.z += f * w.z; acc.w += f * w.w;
    }
    g_hprojT[(h4 + 0) * B_DIM + b] = acc.x;
    g_hprojT[(h4 + 1) * B_DIM + b] = acc.y;
    g_hprojT[(h4 + 2) * B_DIM + b] = acc.z;
    g_hprojT[(h4 + 3) * B_DIM + b] = acc.w;
}

// ---------------------------------------------------------------------------
// HMMA GEMM + fused tanh/v epilogue.
// grid (8 Ntiles [x fastest for A L2-reuse], 512 Mtiles), 256 threads.
// C[m][n] over K via 3 bf16 term-pairs: AhBh + AhBl + AlBh.
// ---------------------------------------------------------------------------
__global__ __launch_bounds__(THREADS, 2)
void score_kernel(const float* __restrict__ v) {
    extern __shared__ char dsm[];
    const int tid  = threadIdx.x;
    const int wid  = tid >> 5;
    const int lane = tid & 31;
    const int Mo = blockIdx.y * BM;
    const int No = blockIdx.x * BN;

    const int wm = (wid & 3) * 32;     // warp M offset in tile
    const int wn = (wid >> 2) * 64;    // warp N offset in tile

    // precomputed ldmatrix offsets
    const int lrow = lane & 15, lk = lane >> 4;
    uint32_t aoff[2][2], boff[4][2];
#pragma unroll
    for (int ks = 0; ks < 2; ks++) {
#pragma unroll
        for (int mt = 0; mt < 2; mt++)
            aoff[mt][ks] = tile_off(wm + mt * 16 + lrow, ks * 2 + lk);
#pragma unroll
        for (int nb = 0; nb < 4; nb++)
            boff[nb][ks] = tile_off(wn + nb * 16 + lrow, ks * 2 + lk);
    }

    const uint32_t smb = smem_u32(dsm);
    float acc[2][8][4];
#pragma unroll
    for (int mt = 0; mt < 2; mt++)
#pragma unroll
        for (int nt = 0; nt < 8; nt++)
#pragma unroll
            for (int i = 0; i < 4; i++) acc[mt][nt][i] = 0.f;

    // ---- stage loader: 8 x 16B cp.async per thread ----
    auto load_stage = [&](int slot, int kt) {
        uint32_t sb = smb + slot * STAGE_BYTES;
#pragma unroll
        for (int i = 0; i < 2; i++) {
            int idx = tid + i * 256;           // 0..511
            int row = idx >> 2, c = idx & 3;
            uint32_t so = tile_off(row, c);
            size_t ga = (size_t)(Mo + row) * K_DIM + kt * BKT + c * 8;
            size_t gb = (size_t)(No + row) * K_DIM + kt * BKT + c * 8;
            cp16(sb + PART_A_H + so, &g_Ah[ga]);
            cp16(sb + PART_A_L + so, &g_Al[ga]);
            cp16(sb + PART_B_H + so, &g_Bh[gb]);
            cp16(sb + PART_B_L + so, &g_Bl[gb]);
        }
    };

    // prologue: fill stages 0..STAGES-2
    load_stage(0, 0); cp_commit();
    load_stage(1, 1); cp_commit();
    cp_wait1();
    __syncthreads();

    for (int kt = 0; kt < KTILES; kt++) {
        if (kt + STAGES - 1 < KTILES)
            load_stage((kt + STAGES - 1) % STAGES, kt + STAGES - 1);
        cp_commit();

        uint32_t sb = smb + (kt % STAGES) * STAGE_BYTES;
#pragma unroll
        for (int term = 0; term < 3; term++) {
            uint32_t Ao = sb + ((term == 2) ? PART_A_L : PART_A_H);
            uint32_t Bo = sb + ((term == 1) ? PART_B_L : PART_B_H);
#pragma unroll
            for (int ks = 0; ks < 2; ks++) {
                uint32_t a0[4], a1[4];
                ldsm4(a0, Ao + aoff[0][ks]);
                ldsm4(a1, Ao + aoff[1][ks]);
                uint32_t bq[4][4];
#pragma unroll
                for (int nb = 0; nb < 4; nb++) ldsm4(bq[nb], Bo + boff[nb][ks]);
#pragma unroll
                for (int nt = 0; nt < 8; nt++) {
                    uint32_t b0 = bq[nt >> 1][nt & 1];
                    uint32_t b1 = bq[nt >> 1][(nt & 1) + 2];
                    mma_bf16(acc[0][nt], a0, b0, b1);
                    mma_bf16(acc[1][nt], a1, b0, b1);
                }
            }
        }
        cp_wait1();
        __syncthreads();
    }

    // ---- epilogue: stage hprojT slice + v into (reused) smem ----
    float* hp_s = reinterpret_cast<float*>(dsm);           // [128][33]
    float* v_s  = reinterpret_cast<float*>(dsm + 128 * 33 * 4);
    float* red  = v_s + 128;                               // [2][128]
    __syncthreads();
    for (int i = tid; i < 128 * 32; i += THREADS) {
        int nl = i >> 5, b = i & 31;
        hp_s[nl * 33 + b] = g_hprojT[(No + nl) * B_DIM + b];
    }
    if (tid < 128) v_s[tid] = v[No + tid];
    __syncthreads();

#pragma unroll
    for (int mt = 0; mt < 2; mt++) {
        int r0 = Mo + wm + mt * 16 + (lane >> 2);
        int b0r = r0 & 31, b1r = (r0 + 8) & 31;
        float s0 = 0.f, s1 = 0.f;
#pragma unroll
        for (int nt = 0; nt < 8; nt++) {
            int nl = wn + nt * 8 + (lane & 3) * 2;
            float vv0 = v_s[nl], vv1 = v_s[nl + 1];
            s0 += vv0 * tanhf(acc[mt][nt][0] + hp_s[nl * 33 + b0r]);
            s0 += vv1 * tanhf(acc[mt][nt][1] + hp_s[(nl + 1) * 33 + b0r]);
            s1 += vv0 * tanhf(acc[mt][nt][2] + hp_s[nl * 33 + b1r]);
            s1 += vv1 * tanhf(acc[mt][nt][3] + hp_s[(nl + 1) * 33 + b1r]);
        }
        s0 += __shfl_xor_sync(0xffffffffu, s0, 1);
        s0 += __shfl_xor_sync(0xffffffffu, s0, 2);
        s1 += __shfl_xor_sync(0xffffffffu, s1, 1);
        s1 += __shfl_xor_sync(0xffffffffu, s1, 2);
        if ((lane & 3) == 0) {
            int rl = wm + mt * 16 + (lane >> 2);
            red[(wid >> 2) * 128 + rl] = s0;
            red[(wid >> 2) * 128 + rl + 8] = s1;
        }
    }
    __syncthreads();
    if (tid < 128)
        g_part[(size_t)blockIdx.x * M_DIM + Mo + tid] = red[tid] + red[128 + tid];
}

// ---------------------------------------------------------------------------
// softmax: sum the 8 N-tile partials, then softmax over S per batch row
// ---------------------------------------------------------------------------
__global__ void softmax_kernel(float* __restrict__ out) {
    __shared__ float srow[S_DIM];
    __shared__ float rd[256];
    const int b = blockIdx.x;
    const int t = threadIdx.x;

    float m = -INFINITY;
    for (int i = t; i < S_DIM; i += 256) {
        int mm = i * B_DIM + b;
        float sc = 0.f;
#pragma unroll
        for (int nt = 0; nt < NTILES; nt++) sc += g_part[(size_t)nt * M_DIM + mm];
        srow[i] = sc;
        m = fmaxf(m, sc);
    }
    rd[t] = m;
    __syncthreads();
    for (int o = 128; o > 0; o >>= 1) { if (t < o) rd[t] = fmaxf(rd[t], rd[t + o]); __syncthreads(); }
    m = rd[0];
    __syncthreads();

    float sum = 0.f;
    for (int i = t; i < S_DIM; i += 256) {
        float e = expf(srow[i] - m);
        srow[i] = e;
        sum += e;
    }
    rd[t] = sum;
    __syncthreads();
    for (int o = 128; o > 0; o >>= 1) { if (t < o) rd[t] += rd[t + o]; __syncthreads(); }
    float inv = 1.f / rd[0];
    __syncthreads();
    float* orow = out + (size_t)b * S_DIM;
    for (int i = t; i < S_DIM; i += 256) orow[i] = srow[i] * inv;
}

// ---------------------------------------------------------------------------
extern "C" void kernel_launch(void* const* d_in, const int* in_sizes, int n_in,
                              void* d_out, int out_size) {
    const float* hidden = (const float*)d_in[0];
    const float* enc    = (const float*)d_in[1];
    const float* W      = (const float*)d_in[2];
    const float* bias   = (const float*)d_in[3];
    const float* v      = (const float*)d_in[4];
    float* out = (float*)d_out;

    cudaFuncSetAttribute(score_kernel, cudaFuncAttributeMaxDynamicSharedMemorySize, DSMEM_BYTES);

    asplit_kernel<<<M_DIM * K_DIM / 2048, 256>>>(enc);
    bsplit_kernel<<<dim3(K_DIM / 32, H_DIM / 32), dim3(32, 8)>>>(W);
    hproj_kernel<<<32, 256>>>(hidden, W, bias);
    score_kernel<<<dim3(NTILES, M_DIM / BM), THREADS, DSMEM_BYTES>>>(v);
    softmax_kernel<<<B_DIM, 256>>>(out);
}

// round 5
// speedup vs baseline: 3.3970x; 1.1153x over previous
#include <cuda_runtime.h>
#include <cuda_bf16.h>
#include <cstdint>
#include <math.h>

#define S_DIM 2048
#define B_DIM 32
#define H_DIM 1024
#define K_DIM 2048
#define M_DIM 65536

#define BM 128
#define BN 128
#define BKT 32
#define KTILES (K_DIM / BKT)     // 64
#define STAGES 3
#define THREADS 256
#define NTILES (H_DIM / BN)      // 8

// stage parts (bytes): Ah | Al | Bh | Bl, each 128 rows x 32 bf16 = 8KB
#define PART_A_H 0
#define PART_A_L 8192
#define PART_B_H 16384
#define PART_B_L 24576
#define STAGE_BYTES 32768
#define DSMEM_BYTES (STAGES * STAGE_BYTES)

// ---------------- device scratch ----------------
__device__ __nv_bfloat16 g_Ah[(size_t)M_DIM * K_DIM];
__device__ __nv_bfloat16 g_Al[(size_t)M_DIM * K_DIM];
__device__ __nv_bfloat16 g_Bh[(size_t)H_DIM * K_DIM];
__device__ __nv_bfloat16 g_Bl[(size_t)H_DIM * K_DIM];
__device__ float g_hpart[8 * B_DIM * H_DIM];  // e-slice partials [sl][b][h]
__device__ float g_hprojT[H_DIM * B_DIM];     // [h][b]
__device__ float g_part[NTILES * M_DIM];      // per-N-tile partial scores [nt][m]

// ---------------- PTX helpers (baseline sm_80+ only) ----------------
__device__ __forceinline__ uint32_t smem_u32(const void* p) {
    uint32_t a;
    asm("{ .reg .u64 t; cvta.to.shared.u64 t, %1; cvt.u32.u64 %0, t; }" : "=r"(a) : "l"(p));
    return a;
}
__device__ __forceinline__ void cp16(uint32_t dst, const void* src) {
    asm volatile("cp.async.cg.shared.global [%0], [%1], 16;" :: "r"(dst), "l"(src) : "memory");
}
__device__ __forceinline__ void cp_commit() {
    asm volatile("cp.async.commit_group;" ::: "memory");
}
__device__ __forceinline__ void cp_wait1() {
    asm volatile("cp.async.wait_group 1;" ::: "memory");
}
__device__ __forceinline__ void ldsm4(uint32_t* r, uint32_t addr) {
    asm volatile("ldmatrix.sync.aligned.m8n8.x4.shared.b16 {%0,%1,%2,%3}, [%4];"
                 : "=r"(r[0]), "=r"(r[1]), "=r"(r[2]), "=r"(r[3]) : "r"(addr));
}
__device__ __forceinline__ void mma_bf16(float* c, const uint32_t* a, uint32_t b0, uint32_t b1) {
    asm volatile("mma.sync.aligned.m16n8k16.row.col.f32.bf16.bf16.f32 "
                 "{%0,%1,%2,%3}, {%4,%5,%6,%7}, {%8,%9}, {%0,%1,%2,%3};"
                 : "+f"(c[0]), "+f"(c[1]), "+f"(c[2]), "+f"(c[3])
                 : "r"(a[0]), "r"(a[1]), "r"(a[2]), "r"(a[3]), "r"(b0), "r"(b1));
}

// swizzled 16B-unit offset inside a 128x32 bf16 tile (conflict-free for
// ldmatrix 8-row phases and the cp.async store pattern)
__device__ __forceinline__ uint32_t tile_off(int row, int c) {
    return (uint32_t)(((row << 2) + (c ^ ((row >> 1) & 3))) << 4);
}

// ---------------------------------------------------------------------------
// Pre-split A (enc, fp32) -> bf16 hi/lo, same [m][k] layout
// ---------------------------------------------------------------------------
__global__ void asplit_kernel(const float* __restrict__ enc) {
    size_t g = ((size_t)blockIdx.x * 256 + threadIdx.x) * 8;
    float4 f0 = *reinterpret_cast<const float4*>(enc + g);
    float4 f1 = *reinterpret_cast<const float4*>(enc + g + 4);
    float x[8] = {f0.x, f0.y, f0.z, f0.w, f1.x, f1.y, f1.z, f1.w};
    uint32_t hh[4], ll[4];
#pragma unroll
    for (int i = 0; i < 4; i++) {
        __nv_bfloat162 h = __floats2bfloat162_rn(x[2 * i], x[2 * i + 1]);
        float2 hf = __bfloat1622float2(h);
        __nv_bfloat162 l = __floats2bfloat162_rn(x[2 * i] - hf.x, x[2 * i + 1] - hf.y);
        hh[i] = *reinterpret_cast<uint32_t*>(&h);
        ll[i] = *reinterpret_cast<uint32_t*>(&l);
    }
    *reinterpret_cast<uint4*>(&g_Ah[g]) = make_uint4(hh[0], hh[1], hh[2], hh[3]);
    *reinterpret_cast<uint4*>(&g_Al[g]) = make_uint4(ll[0], ll[1], ll[2], ll[3]);
}

// ---------------------------------------------------------------------------
// Pre-split + transpose We -> g_Bh/g_Bl [n][k], smem tile transpose
// ---------------------------------------------------------------------------
__global__ void bsplit_kernel(const float* __restrict__ W) {
    __shared__ float tile[32][33];
    const int k0 = blockIdx.x * 32;
    const int n0 = blockIdx.y * 32;
    const int tx = threadIdx.x;        // 32
    const int ty = threadIdx.y;        // 8
#pragma unroll
    for (int r = 0; r < 4; r++) {
        int k = ty * 4 + r;
        tile[k][tx] = W[(size_t)(H_DIM + k0 + k) * H_DIM + n0 + tx];
    }
    __syncthreads();
#pragma unroll
    for (int r = 0; r < 4; r++) {
        int n = ty * 4 + r;
        float w = tile[tx][n];
        __nv_bfloat16 h = __float2bfloat16_rn(w);
        float l = w - __bfloat162float(h);
        size_t o = (size_t)(n0 + n) * K_DIM + k0 + tx;
        g_Bh[o] = h;
        g_Bl[o] = __float2bfloat16_rn(l);
    }
}

// ---------------------------------------------------------------------------
// hproj stage 1: e-slice partials.  grid (32 b, 8 slices), 256 threads.
// g_hpart[sl][b][h] = sum_{e in slice} hidden[b][e] * W[e][h]
// ---------------------------------------------------------------------------
__global__ void hproj1_kernel(const float* __restrict__ hidden,
                              const float* __restrict__ W) {
    const int b  = blockIdx.x;
    const int sl = blockIdx.y;
    const int h4 = threadIdx.x * 4;
    const float* hr = hidden + b * H_DIM + sl * 128;
    float4 acc = make_float4(0.f, 0.f, 0.f, 0.f);
#pragma unroll 8
    for (int e = 0; e < 128; e++) {
        float f = hr[e];
        float4 w = *reinterpret_cast<const float4*>(
            &W[(size_t)(sl * 128 + e) * H_DIM + h4]);
        acc.x += f * w.x; acc.y += f * w.y; acc.z += f * w.z; acc.w += f * w.w;
    }
    *reinterpret_cast<float4*>(&g_hpart[((size_t)sl * B_DIM + b) * H_DIM + h4]) = acc;
}

// hproj stage 2: combine slices + bias, store transposed [h][b]
__global__ void hproj2_kernel(const float* __restrict__ bias) {
    int g = blockIdx.x * 256 + threadIdx.x;   // 0..8191
    int b = g >> 8;
    int h4 = (g & 255) * 4;
    float4 acc = make_float4(bias[h4], bias[h4 + 1], bias[h4 + 2], bias[h4 + 3]);
#pragma unroll
    for (int sl = 0; sl < 8; sl++) {
        float4 p = *reinterpret_cast<const float4*>(
            &g_hpart[((size_t)sl * B_DIM + b) * H_DIM + h4]);
        acc.x += p.x; acc.y += p.y; acc.z += p.z; acc.w += p.w;
    }
    g_hprojT[(h4 + 0) * B_DIM + b] = acc.x;
    g_hprojT[(h4 + 1) * B_DIM + b] = acc.y;
    g_hprojT[(h4 + 2) * B_DIM + b] = acc.z;
    g_hprojT[(h4 + 3) * B_DIM + b] = acc.w;
}

// ---------------------------------------------------------------------------
// HMMA GEMM + fused tanh/v epilogue.
// grid (8 Ntiles [x fastest for A L2-reuse], 512 Mtiles), 256 threads.
// C[m][n] over K via 3 bf16 term-pairs: AhBh + AlBh + AhBl.
// ---------------------------------------------------------------------------
__global__ __launch_bounds__(THREADS, 2)
void score_kernel(const float* __restrict__ v) {
    extern __shared__ char dsm[];
    const int tid  = threadIdx.x;
    const int wid  = tid >> 5;
    const int lane = tid & 31;
    const int Mo = blockIdx.y * BM;
    const int No = blockIdx.x * BN;

    const int wm = (wid & 3) * 32;     // warp M offset in tile
    const int wn = (wid >> 2) * 64;    // warp N offset in tile

    // precomputed ldmatrix offsets
    const int lrow = lane & 15, lk = lane >> 4;
    uint32_t aoff[2][2], boff[4][2];
#pragma unroll
    for (int ks = 0; ks < 2; ks++) {
#pragma unroll
        for (int mt = 0; mt < 2; mt++)
            aoff[mt][ks] = tile_off(wm + mt * 16 + lrow, ks * 2 + lk);
#pragma unroll
        for (int nb = 0; nb < 4; nb++)
            boff[nb][ks] = tile_off(wn + nb * 16 + lrow, ks * 2 + lk);
    }

    // precomputed cp.async pointers (advance +64B per kt) and smem offsets
    const char* pA[2];   // row pointers into g_Ah (g_Al at fixed byte delta)
    const char* pB[2];
    uint32_t so[2];
#pragma unroll
    for (int i = 0; i < 2; i++) {
        int idx = tid + i * 256;
        int row = idx >> 2, c = idx & 3;
        so[i] = tile_off(row, c);
        pA[i] = reinterpret_cast<const char*>(&g_Ah[(size_t)(Mo + row) * K_DIM + c * 8]);
        pB[i] = reinterpret_cast<const char*>(&g_Bh[(size_t)(No + row) * K_DIM + c * 8]);
    }
    const size_t dAL = (const char*)g_Al - (const char*)g_Ah;
    const size_t dBL = (const char*)g_Bl - (const char*)g_Bh;

    const uint32_t smb = smem_u32(dsm);
    float acc[2][8][4];
#pragma unroll
    for (int mt = 0; mt < 2; mt++)
#pragma unroll
        for (int nt = 0; nt < 8; nt++)
#pragma unroll
            for (int i = 0; i < 4; i++) acc[mt][nt][i] = 0.f;

    auto load_stage = [&](int slot) {
        uint32_t sb = smb + slot * STAGE_BYTES;
#pragma unroll
        for (int i = 0; i < 2; i++) {
            cp16(sb + PART_A_H + so[i], pA[i]);
            cp16(sb + PART_A_L + so[i], pA[i] + dAL);
            cp16(sb + PART_B_H + so[i], pB[i]);
            cp16(sb + PART_B_L + so[i], pB[i] + dBL);
        }
        pA[0] += 64; pA[1] += 64; pB[0] += 64; pB[1] += 64;
    };

    // prologue
    load_stage(0); cp_commit();
    load_stage(1); cp_commit();
    cp_wait1();
    __syncthreads();

    int slot_ld = 2, slot_cp = 0;
    for (int kt = 0; kt < KTILES; kt++) {
        if (kt + STAGES - 1 < KTILES) load_stage(slot_ld);
        cp_commit();
        if (++slot_ld == STAGES) slot_ld = 0;

        uint32_t AH = smb + slot_cp * STAGE_BYTES + PART_A_H;
        uint32_t AL = smb + slot_cp * STAGE_BYTES + PART_A_L;
        uint32_t BH = smb + slot_cp * STAGE_BYTES + PART_B_H;
        uint32_t BL = smb + slot_cp * STAGE_BYTES + PART_B_L;
        if (++slot_cp == STAGES) slot_cp = 0;

#pragma unroll
        for (int ks = 0; ks < 2; ks++) {
            uint32_t ah0[4], ah1[4], bq[4][4];
            ldsm4(ah0, AH + aoff[0][ks]);
            ldsm4(ah1, AH + aoff[1][ks]);
#pragma unroll
            for (int nb = 0; nb < 4; nb++) ldsm4(bq[nb], BH + boff[nb][ks]);
#pragma unroll
            for (int nt = 0; nt < 8; nt++) {
                uint32_t b0 = bq[nt >> 1][nt & 1];
                uint32_t b1 = bq[nt >> 1][(nt & 1) + 2];
                mma_bf16(acc[0][nt], ah0, b0, b1);
                mma_bf16(acc[1][nt], ah1, b0, b1);
            }
            // Al * Bh  (Bh fragments still live)
            uint32_t al0[4], al1[4];
            ldsm4(al0, AL + aoff[0][ks]);
            ldsm4(al1, AL + aoff[1][ks]);
#pragma unroll
            for (int nt = 0; nt < 8; nt++) {
                uint32_t b0 = bq[nt >> 1][nt & 1];
                uint32_t b1 = bq[nt >> 1][(nt & 1) + 2];
                mma_bf16(acc[0][nt], al0, b0, b1);
                mma_bf16(acc[1][nt], al1, b0, b1);
            }
            // Ah * Bl  (Ah fragments still live; Bl overwrites Bh's registers)
            uint32_t cq[4][4];
#pragma unroll
            for (int nb = 0; nb < 4; nb++) ldsm4(cq[nb], BL + boff[nb][ks]);
#pragma unroll
            for (int nt = 0; nt < 8; nt++) {
                uint32_t b0 = cq[nt >> 1][nt & 1];
                uint32_t b1 = cq[nt >> 1][(nt & 1) + 2];
                mma_bf16(acc[0][nt], ah0, b0, b1);
                mma_bf16(acc[1][nt], ah1, b0, b1);
            }
        }
        cp_wait1();
        __syncthreads();
    }

    // ---- epilogue: stage hprojT slice + v into (reused) smem ----
    float* hp_s = reinterpret_cast<float*>(dsm);           // [128][33]
    float* v_s  = reinterpret_cast<float*>(dsm + 128 * 33 * 4);
    float* red  = v_s + 128;                               // [2][128]
    __syncthreads();
    for (int i = tid; i < 128 * 32; i += THREADS) {
        int nl = i >> 5, b = i & 31;
        hp_s[nl * 33 + b] = g_hprojT[(No + nl) * B_DIM + b];
    }
    if (tid < 128) v_s[tid] = v[No + tid];
    __syncthreads();

#pragma unroll
    for (int mt = 0; mt < 2; mt++) {
        int r0 = Mo + wm + mt * 16 + (lane >> 2);
        int b0r = r0 & 31, b1r = (r0 + 8) & 31;
        float s0 = 0.f, s1 = 0.f;
#pragma unroll
        for (int nt = 0; nt < 8; nt++) {
            int nl = wn + nt * 8 + (lane & 3) * 2;
            float vv0 = v_s[nl], vv1 = v_s[nl + 1];
            s0 += vv0 * tanhf(acc[mt][nt][0] + hp_s[nl * 33 + b0r]);
            s0 += vv1 * tanhf(acc[mt][nt][1] + hp_s[(nl + 1) * 33 + b0r]);
            s1 += vv0 * tanhf(acc[mt][nt][2] + hp_s[nl * 33 + b1r]);
            s1 += vv1 * tanhf(acc[mt][nt][3] + hp_s[(nl + 1) * 33 + b1r]);
        }
        s0 += __shfl_xor_sync(0xffffffffu, s0, 1);
        s0 += __shfl_xor_sync(0xffffffffu, s0, 2);
        s1 += __shfl_xor_sync(0xffffffffu, s1, 1);
        s1 += __shfl_xor_sync(0xffffffffu, s1, 2);
        if ((lane & 3) == 0) {
            int rl = wm + mt * 16 + (lane >> 2);
            red[(wid >> 2) * 128 + rl] = s0;
            red[(wid >> 2) * 128 + rl + 8] = s1;
        }
    }
    __syncthreads();
    if (tid < 128)
        g_part[(size_t)blockIdx.x * M_DIM + Mo + tid] = red[tid] + red[128 + tid];
}

// ---------------------------------------------------------------------------
// softmax: sum the 8 N-tile partials, then softmax over S per batch row
// ---------------------------------------------------------------------------
__global__ void softmax_kernel(float* __restrict__ out) {
    __shared__ float srow[S_DIM];
    __shared__ float rd[256];
    const int b = blockIdx.x;
    const int t = threadIdx.x;

    float m = -INFINITY;
    for (int i = t; i < S_DIM; i += 256) {
        int mm = i * B_DIM + b;
        float sc = 0.f;
#pragma unroll
        for (int nt = 0; nt < NTILES; nt++) sc += g_part[(size_t)nt * M_DIM + mm];
        srow[i] = sc;
        m = fmaxf(m, sc);
    }
    rd[t] = m;
    __syncthreads();
    for (int o = 128; o > 0; o >>= 1) { if (t < o) rd[t] = fmaxf(rd[t], rd[t + o]); __syncthreads(); }
    m = rd[0];
    __syncthreads();

    float sum = 0.f;
    for (int i = t; i < S_DIM; i += 256) {
        float e = expf(srow[i] - m);
        srow[i] = e;
        sum += e;
    }
    rd[t] = sum;
    __syncthreads();
    for (int o = 128; o > 0; o >>= 1) { if (t < o) rd[t] += rd[t + o]; __syncthreads(); }
    float inv = 1.f / rd[0];
    __syncthreads();
    float* orow = out + (size_t)b * S_DIM;
    for (int i = t; i < S_DIM; i += 256) orow[i] = srow[i] * inv;
}

// ---------------------------------------------------------------------------
extern "C" void kernel_launch(void* const* d_in, const int* in_sizes, int n_in,
                              void* d_out, int out_size) {
    const float* hidden = (const float*)d_in[0];
    const float* enc    = (const float*)d_in[1];
    const float* W      = (const float*)d_in[2];
    const float* bias   = (const float*)d_in[3];
    const float* v      = (const float*)d_in[4];
    float* out = (float*)d_out;

    cudaFuncSetAttribute(score_kernel, cudaFuncAttributeMaxDynamicSharedMemorySize, DSMEM_BYTES);

    asplit_kernel<<<M_DIM * K_DIM / 2048, 256>>>(enc);
    bsplit_kernel<<<dim3(K_DIM / 32, H_DIM / 32), dim3(32, 8)>>>(W);
    hproj1_kernel<<<dim3(B_DIM, 8), 256>>>(hidden, W);
    hproj2_kernel<<<32, 256>>>(bias);
    score_kernel<<<dim3(NTILES, M_DIM / BM), THREADS, DSMEM_BYTES>>>(v);
    softmax_kernel<<<B_DIM, 256>>>(out);
}